// round 2
// baseline (speedup 1.0000x reference)
#include <cuda_runtime.h>
#include <math.h>

#define D_MODEL 1024
#define NSEQ    2048
#define NB      4
#define NH      16
#define DH      64
#define ROWS    (NB * NSEQ)       // 8192
#define SCALE   0.125f            // 1/sqrt(64)

// ---------------- scratch (no allocations allowed) ----------------
__device__ float g_Q[ROWS * D_MODEL];
__device__ float g_K[ROWS * D_MODEL];
__device__ float g_V[ROWS * D_MODEL];
__device__ float g_S[ROWS * D_MODEL];
__device__ float g_O[ROWS * D_MODEL];
__device__ float g_Mpart[8 * NB * NH * DH * DH];   // split-k partials of K^T V
__device__ float g_M[NB * NH * DH * DH];           // K^T V per (b,h)

// ---------------- SGEMM 128x128x8: C = A*B + bias ----------------
// A: [M,K] row-major, B: [K,N] row-major, bias: [N]
__global__ __launch_bounds__(256, 2) void sgemm_bias_kernel(
    const float* __restrict__ A, const float* __restrict__ B,
    const float* __restrict__ bias, float* __restrict__ C,
    int M, int N, int K)
{
    __shared__ float As[8][128];
    __shared__ float Bs[8][128];
    const int tid = threadIdx.x;
    const int bm = blockIdx.y * 128;
    const int bn = blockIdx.x * 128;
    const int tx = tid & 15;          // 16 col groups of 8
    const int ty = tid >> 4;          // 16 row groups of 8

    const int arow = tid >> 1;        // 0..127
    const int acol = (tid & 1) * 4;   // 0 or 4
    const int brow = tid >> 5;        // 0..7
    const int bcol = (tid & 31) * 4;  // 0..124

    const float* Aptr = A + (size_t)(bm + arow) * K + acol;
    const float* Bptr = B + (size_t)brow * N + bn + bcol;

    float acc[8][8];
#pragma unroll
    for (int i = 0; i < 8; i++)
#pragma unroll
        for (int j = 0; j < 8; j++) acc[i][j] = 0.f;

    for (int k0 = 0; k0 < K; k0 += 8) {
        float4 av = *(const float4*)(Aptr + k0);
        float4 bv = *(const float4*)(Bptr + (size_t)k0 * N);
        As[acol + 0][arow] = av.x;
        As[acol + 1][arow] = av.y;
        As[acol + 2][arow] = av.z;
        As[acol + 3][arow] = av.w;
        *(float4*)&Bs[brow][bcol] = bv;
        __syncthreads();
#pragma unroll
        for (int kk = 0; kk < 8; kk++) {
            float a[8], b[8];
            *(float4*)(a)     = *(const float4*)&As[kk][ty * 8];
            *(float4*)(a + 4) = *(const float4*)&As[kk][ty * 8 + 4];
            *(float4*)(b)     = *(const float4*)&Bs[kk][tx * 8];
            *(float4*)(b + 4) = *(const float4*)&Bs[kk][tx * 8 + 4];
#pragma unroll
            for (int i = 0; i < 8; i++)
#pragma unroll
                for (int j = 0; j < 8; j++) acc[i][j] = fmaf(a[i], b[j], acc[i][j]);
        }
        __syncthreads();
    }
#pragma unroll
    for (int i = 0; i < 8; i++) {
        const int row = bm + ty * 8 + i;
#pragma unroll
        for (int j4 = 0; j4 < 8; j4 += 4) {
            const int c = bn + tx * 8 + j4;
            float4 o;
            o.x = acc[i][j4 + 0] + bias[c + 0];
            o.y = acc[i][j4 + 1] + bias[c + 1];
            o.z = acc[i][j4 + 2] + bias[c + 2];
            o.w = acc[i][j4 + 3] + bias[c + 3];
            *(float4*)(C + (size_t)row * N + c) = o;
        }
    }
}

// ---------------- K^T V partials: per (b,h), split-k over 8 chunks of 256 ----------------
__global__ __launch_bounds__(256) void ktv_partial_kernel(
    const float* __restrict__ Kp, const float* __restrict__ Vp,
    float* __restrict__ Mpart)
{
    const int bh    = blockIdx.x;   // 0..63
    const int chunk = blockIdx.y;   // 0..7
    const int b = bh >> 4, h = bh & 15;
    const int kbase = b * NSEQ + chunk * 256;
    const int col   = h * DH;

    __shared__ float Ks[8][64];
    __shared__ float Vs[8][64];
    const int tid = threadIdx.x;
    const int tdk = (tid & 15) * 4;
    const int tdv = (tid >> 4) * 4;
    const int lane = tid & 127;
    const int lr = lane >> 4;
    const int lc = (lane & 15) * 4;

    float acc[4][4];
#pragma unroll
    for (int i = 0; i < 4; i++)
#pragma unroll
        for (int j = 0; j < 4; j++) acc[i][j] = 0.f;

    for (int k0 = 0; k0 < 256; k0 += 8) {
        const float* src = (tid < 128) ? Kp : Vp;
        float* dst = (tid < 128) ? &Ks[lr][lc] : &Vs[lr][lc];
        *(float4*)dst = *(const float4*)(src + (size_t)(kbase + k0 + lr) * D_MODEL + col + lc);
        __syncthreads();
#pragma unroll
        for (int r = 0; r < 8; r++) {
            float kv[4], vv[4];
            *(float4*)kv = *(const float4*)&Ks[r][tdk];
            *(float4*)vv = *(const float4*)&Vs[r][tdv];
#pragma unroll
            for (int i = 0; i < 4; i++)
#pragma unroll
                for (int j = 0; j < 4; j++) acc[i][j] = fmaf(kv[i], vv[j], acc[i][j]);
        }
        __syncthreads();
    }
    float* Mp = Mpart + ((size_t)chunk * (NB * NH) + bh) * (DH * DH);
#pragma unroll
    for (int i = 0; i < 4; i++)
#pragma unroll
        for (int j = 0; j < 4; j++) Mp[(tdk + i) * DH + tdv + j] = acc[i][j];
}

__global__ void m_reduce_kernel(const float* __restrict__ Mpart, float* __restrict__ Mo)
{
    const int i = blockIdx.x * blockDim.x + threadIdx.x;
    if (i < NB * NH * DH * DH) {
        float s = 0.f;
#pragma unroll
        for (int c = 0; c < 8; c++) s += Mpart[(size_t)c * (NB * NH * DH * DH) + i];
        Mo[i] = s;
    }
}

// ---------------- attention: online softmax stats + beta + Q*M epilogue ----------------
// grid: (32 q-tiles, 16 heads, 4 batches), 256 threads.
// QsT holds SCALE * Q (scale folded once at load; lang dot and Q*M epilogue
// therefore need no extra SCALE factor).
__global__ __launch_bounds__(256) void attn_kernel(
    const float* __restrict__ Q, const float* __restrict__ Kp,
    const float* __restrict__ S, const float* __restrict__ Mo,
    float* __restrict__ O)
{
    const int q0 = blockIdx.x * 64;
    const int h  = blockIdx.y;
    const int b  = blockIdx.z;
    const int rowbase = b * NSEQ;
    const int col = h * DH;
    const int tid = threadIdx.x;

    __shared__ float QsT[64][68];   // [d][q], pre-scaled by SCALE
    __shared__ float KsT[64][68];   // [d][k], later reused as M[dk][dv]
    __shared__ float red_m[64][17];
    __shared__ float red_d[64][17];
    __shared__ float beta_s[64];

    // load Q tile transposed, folding in SCALE
    for (int idx = tid; idx < 1024; idx += 256) {
        const int q = idx >> 4;
        const int d4 = (idx & 15) * 4;
        float4 v = *(const float4*)(Q + (size_t)(rowbase + q0 + q) * D_MODEL + col + d4);
        QsT[d4 + 0][q] = v.x * SCALE; QsT[d4 + 1][q] = v.y * SCALE;
        QsT[d4 + 2][q] = v.z * SCALE; QsT[d4 + 3][q] = v.w * SCALE;
    }
    __syncthreads();

    const int tq = (tid & 15) * 4;   // 4 queries per thread
    const int tk = (tid >> 4) * 4;   // 4 keys (within tile) per thread
    float m_t[4] = {-1e30f, -1e30f, -1e30f, -1e30f};
    float d_t[4] = {0.f, 0.f, 0.f, 0.f};

    for (int kt = 0; kt < NSEQ; kt += 64) {
        for (int idx = tid; idx < 1024; idx += 256) {
            const int kk = idx >> 4;
            const int d4 = (idx & 15) * 4;
            float4 v = *(const float4*)(Kp + (size_t)(rowbase + kt + kk) * D_MODEL + col + d4);
            KsT[d4 + 0][kk] = v.x; KsT[d4 + 1][kk] = v.y;
            KsT[d4 + 2][kk] = v.z; KsT[d4 + 3][kk] = v.w;
        }
        __syncthreads();

        float sc[4][4];
#pragma unroll
        for (int i = 0; i < 4; i++)
#pragma unroll
            for (int j = 0; j < 4; j++) sc[i][j] = 0.f;

#pragma unroll 16
        for (int d = 0; d < 64; d++) {
            float qv[4], kv[4];
            *(float4*)qv = *(const float4*)&QsT[d][tq];
            *(float4*)kv = *(const float4*)&KsT[d][tk];
#pragma unroll
            for (int i = 0; i < 4; i++)
#pragma unroll
                for (int j = 0; j < 4; j++) sc[i][j] = fmaf(qv[i], kv[j], sc[i][j]);
        }
        // branch-free online max/sum-exp update per query (scores already scaled)
#pragma unroll
        for (int i = 0; i < 4; i++) {
            const float s0 = sc[i][0], s1 = sc[i][1];
            const float s2 = sc[i][2], s3 = sc[i][3];
            const float mx = fmaxf(fmaxf(s0, s1), fmaxf(s2, s3));
            const float mnew = fmaxf(m_t[i], mx);
            d_t[i] = d_t[i] * __expf(m_t[i] - mnew)
                   + __expf(s0 - mnew) + __expf(s1 - mnew)
                   + __expf(s2 - mnew) + __expf(s3 - mnew);
            m_t[i] = mnew;
        }
        __syncthreads();
    }

    // cross-thread (16 k-groups) reduction of (max, sumexp)
    const int kg = tid >> 4;
#pragma unroll
    for (int i = 0; i < 4; i++) {
        red_m[tq + i][kg] = m_t[i];
        red_d[tq + i][kg] = d_t[i];
    }
    __syncthreads();

    if (tid < 64) {
        const int q = tid;
        float m = -1e30f;
#pragma unroll
        for (int g = 0; g < 16; g++) m = fmaxf(m, red_m[q][g]);
        float D = 0.f;
#pragma unroll
        for (int g = 0; g < 16; g++) D += red_d[q][g] * __expf(red_m[q][g] - m);
        // lang term: dot(scaled_q, s)
        const float* Srow = S + (size_t)(rowbase + q0 + q) * D_MODEL + col;
        float lg = 0.f;
#pragma unroll 16
        for (int d = 0; d < 64; d++) lg = fmaf(QsT[d][q], Srow[d], lg);
        const float mf = fmaxf(m, lg);
        const float Df = D * __expf(m - mf) + __expf(lg - mf);
        beta_s[q] = __expf(lg - mf) / Df;
    }
    __syncthreads();

    // load M (K^T V) into KsT region: KsT[dk][dv]
    {
        const float* Mp = Mo + (size_t)(b * NH + h) * (DH * DH);
        for (int idx = tid; idx < 1024; idx += 256) {
            const int dk = idx >> 4;
            const int d4 = (idx & 15) * 4;
            *(float4*)&KsT[dk][d4] = *(const float4*)(Mp + dk * DH + d4);
        }
    }
    __syncthreads();

    // att_v = (scaled_Q) @ M ; out = beta*s + (1-beta)*att_v
    {
        const int q   = tid >> 2;
        const int dv0 = (tid & 3) * 16;
        float acc[16];
#pragma unroll
        for (int j = 0; j < 16; j++) acc[j] = 0.f;
#pragma unroll 8
        for (int dk = 0; dk < 64; dk++) {
            const float qv = QsT[dk][q];
#pragma unroll
            for (int j = 0; j < 16; j++) acc[j] = fmaf(qv, KsT[dk][dv0 + j], acc[j]);
        }
        const float beta = beta_s[q];
        const float omb  = 1.f - beta;
        const float* Srow = S + (size_t)(rowbase + q0 + q) * D_MODEL + col + dv0;
        float* Orow = O + (size_t)(rowbase + q0 + q) * D_MODEL + col + dv0;
#pragma unroll
        for (int j4 = 0; j4 < 16; j4 += 4) {
            float4 sv = *(const float4*)(Srow + j4);
            float4 o;
            o.x = beta * sv.x + omb * acc[j4 + 0];
            o.y = beta * sv.y + omb * acc[j4 + 1];
            o.z = beta * sv.z + omb * acc[j4 + 2];
            o.w = beta * sv.w + omb * acc[j4 + 3];
            *(float4*)(Orow + j4) = o;
        }
    }
}

// ---------------- launch ----------------
extern "C" void kernel_launch(void* const* d_in, const int* in_sizes, int n_in,
                              void* d_out, int out_size)
{
    (void)in_sizes; (void)n_in; (void)out_size;
    const float* queries = (const float*)d_in[0];
    const float* keys    = (const float*)d_in[1];
    const float* values  = (const float*)d_in[2];
    const float* langf   = (const float*)d_in[3];
    const float* Wq = (const float*)d_in[4];
    const float* bq = (const float*)d_in[5];
    const float* Wk = (const float*)d_in[6];
    const float* bk = (const float*)d_in[7];
    const float* Wv = (const float*)d_in[8];
    const float* bv = (const float*)d_in[9];
    const float* Ws = (const float*)d_in[10];
    const float* bs = (const float*)d_in[11];
    const float* Wo = (const float*)d_in[12];
    const float* bo = (const float*)d_in[13];

    float *Qp, *Kp, *Vp, *Sp, *Op, *MPp, *Mp;
    cudaGetSymbolAddress((void**)&Qp,  g_Q);
    cudaGetSymbolAddress((void**)&Kp,  g_K);
    cudaGetSymbolAddress((void**)&Vp,  g_V);
    cudaGetSymbolAddress((void**)&Sp,  g_S);
    cudaGetSymbolAddress((void**)&Op,  g_O);
    cudaGetSymbolAddress((void**)&MPp, g_Mpart);
    cudaGetSymbolAddress((void**)&Mp,  g_M);

    dim3 gemm_grid(D_MODEL / 128, ROWS / 128);   // (8, 64)
    sgemm_bias_kernel<<<gemm_grid, 256>>>(queries, Wq, bq, Qp, ROWS, D_MODEL, D_MODEL);
    sgemm_bias_kernel<<<gemm_grid, 256>>>(keys,    Wk, bk, Kp, ROWS, D_MODEL, D_MODEL);
    sgemm_bias_kernel<<<gemm_grid, 256>>>(values,  Wv, bv, Vp, ROWS, D_MODEL, D_MODEL);
    sgemm_bias_kernel<<<gemm_grid, 256>>>(langf,   Ws, bs, Sp, ROWS, D_MODEL, D_MODEL);

    ktv_partial_kernel<<<dim3(NB * NH, 8), 256>>>(Kp, Vp, MPp);
    m_reduce_kernel<<<(NB * NH * DH * DH + 255) / 256, 256>>>(MPp, Mp);

    attn_kernel<<<dim3(NSEQ / 64, NH, NB), 256>>>(Qp, Kp, Sp, Mp, Op);

    sgemm_bias_kernel<<<gemm_grid, 256>>>(Op, Wo, bo, (float*)d_out, ROWS, D_MODEL, D_MODEL);
}

// round 3
// speedup vs baseline: 1.5441x; 1.5441x over previous
#include <cuda_runtime.h>
#include <cuda_bf16.h>
#include <math.h>
#include <stdint.h>

#define D_MODEL 1024
#define NSEQ    2048
#define NB      4
#define NH      16
#define DH      64
#define ROWS    (NB * NSEQ)       // 8192
#define SCALE   0.125f            // 1/sqrt(64)

// ---------------- scratch (no allocations allowed) ----------------
__device__ float g_Q[ROWS * D_MODEL];
__device__ float g_K[ROWS * D_MODEL];
__device__ float g_V[ROWS * D_MODEL];
__device__ float g_S[ROWS * D_MODEL];
__device__ float g_O[ROWS * D_MODEL];
__device__ float g_Mpart[8 * NB * NH * DH * DH];
__device__ float g_M[NB * NH * DH * DH];
__device__ __nv_bfloat16 g_Ahi[ROWS * D_MODEL];
__device__ __nv_bfloat16 g_Alo[ROWS * D_MODEL];
__device__ __nv_bfloat16 g_Bhi[D_MODEL * D_MODEL];
__device__ __nv_bfloat16 g_Blo[D_MODEL * D_MODEL];

// ---------------- fp32 -> bf16 hi/lo split ----------------
__global__ void split_bf16_kernel(const float* __restrict__ X,
                                  __nv_bfloat16* __restrict__ hi,
                                  __nv_bfloat16* __restrict__ lo, int n4)
{
    const int i = blockIdx.x * blockDim.x + threadIdx.x;
    if (i >= n4) return;
    float4 v = ((const float4*)X)[i];
    float xs[4] = {v.x, v.y, v.z, v.w};
    ushort4 H, L;
    unsigned short hs[4], ls[4];
#pragma unroll
    for (int j = 0; j < 4; j++) {
        __nv_bfloat16 h = __float2bfloat16_rn(xs[j]);
        float r = xs[j] - __bfloat162float(h);
        __nv_bfloat16 l = __float2bfloat16_rn(r);
        hs[j] = __bfloat16_as_ushort(h);
        ls[j] = __bfloat16_as_ushort(l);
    }
    H.x = hs[0]; H.y = hs[1]; H.z = hs[2]; H.w = hs[3];
    L.x = ls[0]; L.y = ls[1]; L.z = ls[2]; L.w = ls[3];
    ((ushort4*)hi)[i] = H;
    ((ushort4*)lo)[i] = L;
}

// ---------------- tensor-core GEMM (3x split-bf16) ----------------
// C[M,N] = A[M,K]*B[K,N] + bias, fp32 in/out accuracy ~1e-5.
// CTA tile 128x128, BK=16, 8 warps (4m x 2n), warp tile 32x64.
// smem: double-buffered, chunk-padded for conflict-free ldmatrix.

#define BKT 16
#define A_CH 3                    // 16B chunks per A smem row (2 data + 1 pad)
#define B_CH 17                   // 16B chunks per B smem row (16 data + 1 pad)
#define ST_AHI 0
#define ST_ALO (128 * A_CH * 16)                 // 6144
#define ST_BHI (ST_ALO + 128 * A_CH * 16)        // 12288
#define ST_BLO (ST_BHI + BKT * B_CH * 16)        // 16640
#define STAGE_BYTES (ST_BLO + BKT * B_CH * 16)   // 20992

__device__ __forceinline__ void ldsm4(uint32_t* r, uint32_t addr) {
    asm volatile("ldmatrix.sync.aligned.m8n8.x4.shared.b16 {%0,%1,%2,%3}, [%4];\n"
        : "=r"(r[0]), "=r"(r[1]), "=r"(r[2]), "=r"(r[3]) : "r"(addr));
}
__device__ __forceinline__ void ldsm4t(uint32_t* r, uint32_t addr) {
    asm volatile("ldmatrix.sync.aligned.m8n8.x4.trans.shared.b16 {%0,%1,%2,%3}, [%4];\n"
        : "=r"(r[0]), "=r"(r[1]), "=r"(r[2]), "=r"(r[3]) : "r"(addr));
}
__device__ __forceinline__ void mma_bf16(float* c, const uint32_t* a, uint32_t b0, uint32_t b1) {
    asm volatile("mma.sync.aligned.m16n8k16.row.col.f32.bf16.bf16.f32 "
        "{%0,%1,%2,%3}, {%4,%5,%6,%7}, {%8,%9}, {%0,%1,%2,%3};\n"
        : "+f"(c[0]), "+f"(c[1]), "+f"(c[2]), "+f"(c[3])
        : "r"(a[0]), "r"(a[1]), "r"(a[2]), "r"(a[3]), "r"(b0), "r"(b1));
}
__device__ __forceinline__ void cp16(uint32_t saddr, const void* g) {
    asm volatile("cp.async.cg.shared.global [%0], [%1], 16;\n" :: "r"(saddr), "l"(g));
}
__device__ __forceinline__ void cp_commit() { asm volatile("cp.async.commit_group;\n"); }
__device__ __forceinline__ void cp_wait1()  { asm volatile("cp.async.wait_group 1;\n"); }

__global__ __launch_bounds__(256, 2) void gemm_bf16x3_bias(
    const __nv_bfloat16* __restrict__ Ahi, const __nv_bfloat16* __restrict__ Alo,
    const __nv_bfloat16* __restrict__ Bhi, const __nv_bfloat16* __restrict__ Blo,
    const float* __restrict__ bias, float* __restrict__ C,
    int M, int N, int K)
{
    __shared__ __align__(16) unsigned char sm[2][STAGE_BYTES];
    const int tid  = threadIdx.x;
    const int lane = tid & 31;
    const int w    = tid >> 5;
    const int wm   = (w & 3) * 32;     // warp row offset
    const int wn   = (w >> 2) * 64;    // warp col offset
    const int bm   = blockIdx.y * 128;
    const int bn   = blockIdx.x * 128;

    const uint32_t sbase = (uint32_t)__cvta_generic_to_shared(&sm[0][0]);

    // cp.async mapping: A tile 128x16 bf16 = 128 rows x 2 chunks; B tile 16x128 = 16 rows x 16 chunks
    const int arow = tid >> 1, ac8 = tid & 1;
    const int brow = tid >> 4, bc8 = tid & 15;
    const __nv_bfloat16* gAhi = Ahi + (size_t)(bm + arow) * K + ac8 * 8;
    const __nv_bfloat16* gAlo = Alo + (size_t)(bm + arow) * K + ac8 * 8;
    const __nv_bfloat16* gBhi = Bhi + (size_t)brow * N + bn + bc8 * 8;
    const __nv_bfloat16* gBlo = Blo + (size_t)brow * N + bn + bc8 * 8;
    const uint32_t sAoff = (uint32_t)(arow * A_CH + ac8) * 16;
    const uint32_t sBoff = (uint32_t)(brow * B_CH + bc8) * 16;

    // ldmatrix per-thread addressing
    const int mIdx = lane >> 3, mrow = lane & 7;
    const int a_srow0 = wm + (mIdx & 1) * 8 + mrow;   // + mf*16
    const int a_kch   = mIdx >> 1;                    // 0 or 1
    const int b_srow  = (mIdx & 1) * 8 + mrow;
    const int b_nch0  = (wn >> 3) + (mIdx >> 1);      // + nb*2

    float acc[2][8][4];
#pragma unroll
    for (int i = 0; i < 2; i++)
#pragma unroll
        for (int j = 0; j < 8; j++)
#pragma unroll
            for (int q = 0; q < 4; q++) acc[i][j][q] = 0.f;

    const int NT = K / BKT;   // 64

    // prologue: stages 0,1
#pragma unroll
    for (int s = 0; s < 2; s++) {
        const uint32_t sb = sbase + s * STAGE_BYTES;
        cp16(sb + ST_AHI + sAoff, gAhi + s * BKT);
        cp16(sb + ST_ALO + sAoff, gAlo + s * BKT);
        cp16(sb + ST_BHI + sBoff, gBhi + (size_t)s * BKT * N);
        cp16(sb + ST_BLO + sBoff, gBlo + (size_t)s * BKT * N);
        cp_commit();
    }

    for (int t = 0; t < NT; t++) {
        cp_wait1();
        __syncthreads();
        const uint32_t sb = sbase + (t & 1) * STAGE_BYTES;

        uint32_t ahi[2][4], alo[2][4];
#pragma unroll
        for (int mf = 0; mf < 2; mf++) {
            const uint32_t arow_ch = (uint32_t)((a_srow0 + mf * 16) * A_CH + a_kch) * 16;
            ldsm4(ahi[mf], sb + ST_AHI + arow_ch);
            ldsm4(alo[mf], sb + ST_ALO + arow_ch);
        }
#pragma unroll
        for (int nb = 0; nb < 4; nb++) {
            uint32_t bh[4], bl[4];
            const uint32_t boff = (uint32_t)(b_srow * B_CH + b_nch0 + nb * 2) * 16;
            ldsm4t(bh, sb + ST_BHI + boff);
            ldsm4t(bl, sb + ST_BLO + boff);
#pragma unroll
            for (int mf = 0; mf < 2; mf++) {
#pragma unroll
                for (int sub = 0; sub < 2; sub++) {
                    float* c = acc[mf][nb * 2 + sub];
                    mma_bf16(c, ahi[mf], bh[sub * 2], bh[sub * 2 + 1]);
                    mma_bf16(c, ahi[mf], bl[sub * 2], bl[sub * 2 + 1]);
                    mma_bf16(c, alo[mf], bh[sub * 2], bh[sub * 2 + 1]);
                }
            }
        }
        __syncthreads();
        if (t + 2 < NT) {
            const int kt = t + 2;
            const uint32_t sb2 = sbase + (t & 1) * STAGE_BYTES;
            cp16(sb2 + ST_AHI + sAoff, gAhi + kt * BKT);
            cp16(sb2 + ST_ALO + sAoff, gAlo + kt * BKT);
            cp16(sb2 + ST_BHI + sBoff, gBhi + (size_t)kt * BKT * N);
            cp16(sb2 + ST_BLO + sBoff, gBlo + (size_t)kt * BKT * N);
            cp_commit();
        } else {
            cp_commit();   // keep group count in sync for wait_group 1
        }
    }

    // epilogue: fragment layout c0,c1=(g, 2tg..2tg+1), c2,c3=(g+8, ...)
    const int g  = lane >> 2;
    const int tg = lane & 3;
#pragma unroll
    for (int mf = 0; mf < 2; mf++) {
        const int row0 = bm + wm + mf * 16 + g;
#pragma unroll
        for (int nf = 0; nf < 8; nf++) {
            const int col = bn + wn + nf * 8 + tg * 2;
            const float2 bv = *(const float2*)(bias + col);
            float2 o0, o1;
            o0.x = acc[mf][nf][0] + bv.x;
            o0.y = acc[mf][nf][1] + bv.y;
            o1.x = acc[mf][nf][2] + bv.x;
            o1.y = acc[mf][nf][3] + bv.y;
            *(float2*)(C + (size_t)row0 * N + col)       = o0;
            *(float2*)(C + (size_t)(row0 + 8) * N + col) = o1;
        }
    }
}

// ---------------- K^T V partials: per (b,h), split-k over 8 chunks of 256 ----------------
__global__ __launch_bounds__(256) void ktv_partial_kernel(
    const float* __restrict__ Kp, const float* __restrict__ Vp,
    float* __restrict__ Mpart)
{
    const int bh    = blockIdx.x;
    const int chunk = blockIdx.y;
    const int b = bh >> 4, h = bh & 15;
    const int kbase = b * NSEQ + chunk * 256;
    const int col   = h * DH;

    __shared__ float Ks[8][64];
    __shared__ float Vs[8][64];
    const int tid = threadIdx.x;
    const int tdk = (tid & 15) * 4;
    const int tdv = (tid >> 4) * 4;
    const int lane = tid & 127;
    const int lr = lane >> 4;
    const int lc = (lane & 15) * 4;

    float acc[4][4];
#pragma unroll
    for (int i = 0; i < 4; i++)
#pragma unroll
        for (int j = 0; j < 4; j++) acc[i][j] = 0.f;

    for (int k0 = 0; k0 < 256; k0 += 8) {
        const float* src = (tid < 128) ? Kp : Vp;
        float* dst = (tid < 128) ? &Ks[lr][lc] : &Vs[lr][lc];
        *(float4*)dst = *(const float4*)(src + (size_t)(kbase + k0 + lr) * D_MODEL + col + lc);
        __syncthreads();
#pragma unroll
        for (int r = 0; r < 8; r++) {
            float kv[4], vv[4];
            *(float4*)kv = *(const float4*)&Ks[r][tdk];
            *(float4*)vv = *(const float4*)&Vs[r][tdv];
#pragma unroll
            for (int i = 0; i < 4; i++)
#pragma unroll
                for (int j = 0; j < 4; j++) acc[i][j] = fmaf(kv[i], vv[j], acc[i][j]);
        }
        __syncthreads();
    }
    float* Mp = Mpart + ((size_t)chunk * (NB * NH) + bh) * (DH * DH);
#pragma unroll
    for (int i = 0; i < 4; i++)
#pragma unroll
        for (int j = 0; j < 4; j++) Mp[(tdk + i) * DH + tdv + j] = acc[i][j];
}

__global__ void m_reduce_kernel(const float* __restrict__ Mpart, float* __restrict__ Mo)
{
    const int i = blockIdx.x * blockDim.x + threadIdx.x;
    if (i < NB * NH * DH * DH) {
        float s = 0.f;
#pragma unroll
        for (int c = 0; c < 8; c++) s += Mpart[(size_t)c * (NB * NH * DH * DH) + i];
        Mo[i] = s;
    }
}

// ---------------- attention: online softmax stats + beta + Q*M epilogue ----------------
__global__ __launch_bounds__(256) void attn_kernel(
    const float* __restrict__ Q, const float* __restrict__ Kp,
    const float* __restrict__ S, const float* __restrict__ Mo,
    float* __restrict__ O)
{
    const int q0 = blockIdx.x * 64;
    const int h  = blockIdx.y;
    const int b  = blockIdx.z;
    const int rowbase = b * NSEQ;
    const int col = h * DH;
    const int tid = threadIdx.x;

    __shared__ float QsT[64][68];   // [d][q], pre-scaled by SCALE
    __shared__ float KsT[64][68];   // [d][k], later reused as M[dk][dv]
    __shared__ float red_m[64][17];
    __shared__ float red_d[64][17];
    __shared__ float beta_s[64];

    for (int idx = tid; idx < 1024; idx += 256) {
        const int q = idx >> 4;
        const int d4 = (idx & 15) * 4;
        float4 v = *(const float4*)(Q + (size_t)(rowbase + q0 + q) * D_MODEL + col + d4);
        QsT[d4 + 0][q] = v.x * SCALE; QsT[d4 + 1][q] = v.y * SCALE;
        QsT[d4 + 2][q] = v.z * SCALE; QsT[d4 + 3][q] = v.w * SCALE;
    }
    __syncthreads();

    const int tq = (tid & 15) * 4;
    const int tk = (tid >> 4) * 4;
    float m_t[4] = {-1e30f, -1e30f, -1e30f, -1e30f};
    float d_t[4] = {0.f, 0.f, 0.f, 0.f};

    for (int kt = 0; kt < NSEQ; kt += 64) {
        for (int idx = tid; idx < 1024; idx += 256) {
            const int kk = idx >> 4;
            const int d4 = (idx & 15) * 4;
            float4 v = *(const float4*)(Kp + (size_t)(rowbase + kt + kk) * D_MODEL + col + d4);
            KsT[d4 + 0][kk] = v.x; KsT[d4 + 1][kk] = v.y;
            KsT[d4 + 2][kk] = v.z; KsT[d4 + 3][kk] = v.w;
        }
        __syncthreads();

        float sc[4][4];
#pragma unroll
        for (int i = 0; i < 4; i++)
#pragma unroll
            for (int j = 0; j < 4; j++) sc[i][j] = 0.f;

#pragma unroll 16
        for (int d = 0; d < 64; d++) {
            float qv[4], kv[4];
            *(float4*)qv = *(const float4*)&QsT[d][tq];
            *(float4*)kv = *(const float4*)&KsT[d][tk];
#pragma unroll
            for (int i = 0; i < 4; i++)
#pragma unroll
                for (int j = 0; j < 4; j++) sc[i][j] = fmaf(qv[i], kv[j], sc[i][j]);
        }
#pragma unroll
        for (int i = 0; i < 4; i++) {
            const float s0 = sc[i][0], s1 = sc[i][1];
            const float s2 = sc[i][2], s3 = sc[i][3];
            const float mx = fmaxf(fmaxf(s0, s1), fmaxf(s2, s3));
            const float mnew = fmaxf(m_t[i], mx);
            d_t[i] = d_t[i] * __expf(m_t[i] - mnew)
                   + __expf(s0 - mnew) + __expf(s1 - mnew)
                   + __expf(s2 - mnew) + __expf(s3 - mnew);
            m_t[i] = mnew;
        }
        __syncthreads();
    }

    const int kg = tid >> 4;
#pragma unroll
    for (int i = 0; i < 4; i++) {
        red_m[tq + i][kg] = m_t[i];
        red_d[tq + i][kg] = d_t[i];
    }
    __syncthreads();

    if (tid < 64) {
        const int q = tid;
        float m = -1e30f;
#pragma unroll
        for (int g = 0; g < 16; g++) m = fmaxf(m, red_m[q][g]);
        float D = 0.f;
#pragma unroll
        for (int g = 0; g < 16; g++) D += red_d[q][g] * __expf(red_m[q][g] - m);
        const float* Srow = S + (size_t)(rowbase + q0 + q) * D_MODEL + col;
        float lg = 0.f;
#pragma unroll 16
        for (int d = 0; d < 64; d++) lg = fmaf(QsT[d][q], Srow[d], lg);
        const float mf = fmaxf(m, lg);
        const float Df = D * __expf(m - mf) + __expf(lg - mf);
        beta_s[q] = __expf(lg - mf) / Df;
    }
    __syncthreads();

    {
        const float* Mp = Mo + (size_t)(b * NH + h) * (DH * DH);
        for (int idx = tid; idx < 1024; idx += 256) {
            const int dk = idx >> 4;
            const int d4 = (idx & 15) * 4;
            *(float4*)&KsT[dk][d4] = *(const float4*)(Mp + dk * DH + d4);
        }
    }
    __syncthreads();

    {
        const int q   = tid >> 2;
        const int dv0 = (tid & 3) * 16;
        float acc[16];
#pragma unroll
        for (int j = 0; j < 16; j++) acc[j] = 0.f;
#pragma unroll 8
        for (int dk = 0; dk < 64; dk++) {
            const float qv = QsT[dk][q];
#pragma unroll
            for (int j = 0; j < 16; j++) acc[j] = fmaf(qv, KsT[dk][dv0 + j], acc[j]);
        }
        const float beta = beta_s[q];
        const float omb  = 1.f - beta;
        const float* Srow = S + (size_t)(rowbase + q0 + q) * D_MODEL + col + dv0;
        float* Orow = O + (size_t)(rowbase + q0 + q) * D_MODEL + col + dv0;
#pragma unroll
        for (int j4 = 0; j4 < 16; j4 += 4) {
            float4 sv = *(const float4*)(Srow + j4);
            float4 o;
            o.x = beta * sv.x + omb * acc[j4 + 0];
            o.y = beta * sv.y + omb * acc[j4 + 1];
            o.z = beta * sv.z + omb * acc[j4 + 2];
            o.w = beta * sv.w + omb * acc[j4 + 3];
            *(float4*)(Orow + j4) = o;
        }
    }
}

// ---------------- launch ----------------
extern "C" void kernel_launch(void* const* d_in, const int* in_sizes, int n_in,
                              void* d_out, int out_size)
{
    (void)in_sizes; (void)n_in; (void)out_size;
    const float* queries = (const float*)d_in[0];
    const float* keys    = (const float*)d_in[1];
    const float* values  = (const float*)d_in[2];
    const float* langf   = (const float*)d_in[3];
    const float* Wq = (const float*)d_in[4];
    const float* bq = (const float*)d_in[5];
    const float* Wk = (const float*)d_in[6];
    const float* bk = (const float*)d_in[7];
    const float* Wv = (const float*)d_in[8];
    const float* bv = (const float*)d_in[9];
    const float* Ws = (const float*)d_in[10];
    const float* bs = (const float*)d_in[11];
    const float* Wo = (const float*)d_in[12];
    const float* bo = (const float*)d_in[13];

    float *Qp, *Kp, *Vp, *Sp, *Op, *MPp, *Mp;
    __nv_bfloat16 *Ahi, *Alo, *Bhi, *Blo;
    cudaGetSymbolAddress((void**)&Qp,  g_Q);
    cudaGetSymbolAddress((void**)&Kp,  g_K);
    cudaGetSymbolAddress((void**)&Vp,  g_V);
    cudaGetSymbolAddress((void**)&Sp,  g_S);
    cudaGetSymbolAddress((void**)&Op,  g_O);
    cudaGetSymbolAddress((void**)&MPp, g_Mpart);
    cudaGetSymbolAddress((void**)&Mp,  g_M);
    cudaGetSymbolAddress((void**)&Ahi, g_Ahi);
    cudaGetSymbolAddress((void**)&Alo, g_Alo);
    cudaGetSymbolAddress((void**)&Bhi, g_Bhi);
    cudaGetSymbolAddress((void**)&Blo, g_Blo);

    const int nA4 = ROWS * D_MODEL / 4;        // 2097152
    const int nW4 = D_MODEL * D_MODEL / 4;     // 262144
    dim3 gemm_grid(D_MODEL / 128, ROWS / 128); // (8, 64)

    struct { const float* X; const float* W; const float* bvec; float* C; } proj[4] = {
        {queries, Wq, bq, Qp}, {keys, Wk, bk, Kp}, {values, Wv, bv, Vp}, {langf, Ws, bs, Sp}
    };
    for (int p = 0; p < 4; p++) {
        split_bf16_kernel<<<(nA4 + 255) / 256, 256>>>(proj[p].X, Ahi, Alo, nA4);
        split_bf16_kernel<<<(nW4 + 255) / 256, 256>>>(proj[p].W, Bhi, Blo, nW4);
        gemm_bf16x3_bias<<<gemm_grid, 256>>>(Ahi, Alo, Bhi, Blo, proj[p].bvec, proj[p].C,
                                             ROWS, D_MODEL, D_MODEL);
    }

    ktv_partial_kernel<<<dim3(NB * NH, 8), 256>>>(Kp, Vp, MPp);
    m_reduce_kernel<<<(NB * NH * DH * DH + 255) / 256, 256>>>(MPp, Mp);

    attn_kernel<<<dim3(NSEQ / 64, NH, NB), 256>>>(Qp, Kp, Sp, Mp, Op);

    split_bf16_kernel<<<(nA4 + 255) / 256, 256>>>(Op, Ahi, Alo, nA4);
    split_bf16_kernel<<<(nW4 + 255) / 256, 256>>>(Wo, Bhi, Blo, nW4);
    gemm_bf16x3_bias<<<gemm_grid, 256>>>(Ahi, Alo, Bhi, Blo, bo, (float*)d_out,
                                         ROWS, D_MODEL, D_MODEL);
}

// round 4
// speedup vs baseline: 2.3119x; 1.4972x over previous
#include <cuda_runtime.h>
#include <cuda_bf16.h>
#include <math.h>
#include <stdint.h>

#define D_MODEL 1024
#define NSEQ    2048
#define NB      4
#define NH      16
#define DH      64
#define ROWS    (NB * NSEQ)       // 8192
#define SCALE   0.125f            // 1/sqrt(64)
#define K2SCALE 0.18033688011112042f   // SCALE * log2(e)

// ---------------- scratch (no allocations allowed) ----------------
__device__ float g_Q[ROWS * D_MODEL];
__device__ float g_K[ROWS * D_MODEL];
__device__ float g_V[ROWS * D_MODEL];
__device__ float g_S[ROWS * D_MODEL];
__device__ float g_O[ROWS * D_MODEL];
__device__ float g_Mpart[8 * NB * NH * DH * DH];
__device__ float g_M[NB * NH * DH * DH];
__device__ __nv_bfloat16 g_Ahi[ROWS * D_MODEL];
__device__ __nv_bfloat16 g_Alo[ROWS * D_MODEL];
__device__ __nv_bfloat16 g_Bhi[D_MODEL * D_MODEL];
__device__ __nv_bfloat16 g_Blo[D_MODEL * D_MODEL];
__device__ __nv_bfloat16 g_Qhi[ROWS * D_MODEL];
__device__ __nv_bfloat16 g_Qlo[ROWS * D_MODEL];
__device__ __nv_bfloat16 g_Khi[ROWS * D_MODEL];
__device__ __nv_bfloat16 g_Klo[ROWS * D_MODEL];

__device__ __forceinline__ float ex2f(float x) {
    float y; asm("ex2.approx.f32 %0, %1;" : "=f"(y) : "f"(x)); return y;
}

// ---------------- fp32 -> bf16 hi/lo split (optionally scaled) ----------------
__global__ void split_bf16_kernel(const float* __restrict__ X,
                                  __nv_bfloat16* __restrict__ hi,
                                  __nv_bfloat16* __restrict__ lo, int n4, float scale)
{
    const int i = blockIdx.x * blockDim.x + threadIdx.x;
    if (i >= n4) return;
    float4 v = ((const float4*)X)[i];
    float xs[4] = {v.x * scale, v.y * scale, v.z * scale, v.w * scale};
    ushort4 H, L;
    unsigned short hs[4], ls[4];
#pragma unroll
    for (int j = 0; j < 4; j++) {
        __nv_bfloat16 h = __float2bfloat16_rn(xs[j]);
        float r = xs[j] - __bfloat162float(h);
        __nv_bfloat16 l = __float2bfloat16_rn(r);
        hs[j] = __bfloat16_as_ushort(h);
        ls[j] = __bfloat16_as_ushort(l);
    }
    H.x = hs[0]; H.y = hs[1]; H.z = hs[2]; H.w = hs[3];
    L.x = ls[0]; L.y = ls[1]; L.z = ls[2]; L.w = ls[3];
    ((ushort4*)hi)[i] = H;
    ((ushort4*)lo)[i] = L;
}

// ---------------- common PTX helpers ----------------
__device__ __forceinline__ void ldsm4(uint32_t* r, uint32_t addr) {
    asm volatile("ldmatrix.sync.aligned.m8n8.x4.shared.b16 {%0,%1,%2,%3}, [%4];\n"
        : "=r"(r[0]), "=r"(r[1]), "=r"(r[2]), "=r"(r[3]) : "r"(addr));
}
__device__ __forceinline__ void ldsm4t(uint32_t* r, uint32_t addr) {
    asm volatile("ldmatrix.sync.aligned.m8n8.x4.trans.shared.b16 {%0,%1,%2,%3}, [%4];\n"
        : "=r"(r[0]), "=r"(r[1]), "=r"(r[2]), "=r"(r[3]) : "r"(addr));
}
__device__ __forceinline__ void mma_bf16(float* c, const uint32_t* a, uint32_t b0, uint32_t b1) {
    asm volatile("mma.sync.aligned.m16n8k16.row.col.f32.bf16.bf16.f32 "
        "{%0,%1,%2,%3}, {%4,%5,%6,%7}, {%8,%9}, {%0,%1,%2,%3};\n"
        : "+f"(c[0]), "+f"(c[1]), "+f"(c[2]), "+f"(c[3])
        : "r"(a[0]), "r"(a[1]), "r"(a[2]), "r"(a[3]), "r"(b0), "r"(b1));
}
__device__ __forceinline__ void cp16(uint32_t saddr, const void* g) {
    asm volatile("cp.async.cg.shared.global [%0], [%1], 16;\n" :: "r"(saddr), "l"(g));
}
__device__ __forceinline__ void cp_commit() { asm volatile("cp.async.commit_group;\n"); }
__device__ __forceinline__ void cp_wait1()  { asm volatile("cp.async.wait_group 1;\n"); }
__device__ __forceinline__ void cp_wait0()  { asm volatile("cp.async.wait_group 0;\n"); }

// ---------------- tensor-core GEMM (3x split-bf16), unchanged ----------------
#define BKT 16
#define A_CH 3
#define B_CH 17
#define ST_AHI 0
#define ST_ALO (128 * A_CH * 16)
#define ST_BHI (ST_ALO + 128 * A_CH * 16)
#define ST_BLO (ST_BHI + BKT * B_CH * 16)
#define STAGE_BYTES (ST_BLO + BKT * B_CH * 16)

__global__ __launch_bounds__(256, 2) void gemm_bf16x3_bias(
    const __nv_bfloat16* __restrict__ Ahi, const __nv_bfloat16* __restrict__ Alo,
    const __nv_bfloat16* __restrict__ Bhi, const __nv_bfloat16* __restrict__ Blo,
    const float* __restrict__ bias, float* __restrict__ C,
    int M, int N, int K)
{
    __shared__ __align__(16) unsigned char sm[2][STAGE_BYTES];
    const int tid  = threadIdx.x;
    const int lane = tid & 31;
    const int w    = tid >> 5;
    const int wm   = (w & 3) * 32;
    const int wn   = (w >> 2) * 64;
    const int bm   = blockIdx.y * 128;
    const int bn   = blockIdx.x * 128;

    const uint32_t sbase = (uint32_t)__cvta_generic_to_shared(&sm[0][0]);

    const int arow = tid >> 1, ac8 = tid & 1;
    const int brow = tid >> 4, bc8 = tid & 15;
    const __nv_bfloat16* gAhi = Ahi + (size_t)(bm + arow) * K + ac8 * 8;
    const __nv_bfloat16* gAlo = Alo + (size_t)(bm + arow) * K + ac8 * 8;
    const __nv_bfloat16* gBhi = Bhi + (size_t)brow * N + bn + bc8 * 8;
    const __nv_bfloat16* gBlo = Blo + (size_t)brow * N + bn + bc8 * 8;
    const uint32_t sAoff = (uint32_t)(arow * A_CH + ac8) * 16;
    const uint32_t sBoff = (uint32_t)(brow * B_CH + bc8) * 16;

    const int mIdx = lane >> 3, mrow = lane & 7;
    const int a_srow0 = wm + (mIdx & 1) * 8 + mrow;
    const int a_kch   = mIdx >> 1;
    const int b_srow  = (mIdx & 1) * 8 + mrow;
    const int b_nch0  = (wn >> 3) + (mIdx >> 1);

    float acc[2][8][4];
#pragma unroll
    for (int i = 0; i < 2; i++)
#pragma unroll
        for (int j = 0; j < 8; j++)
#pragma unroll
            for (int q = 0; q < 4; q++) acc[i][j][q] = 0.f;

    const int NT = K / BKT;

#pragma unroll
    for (int s = 0; s < 2; s++) {
        const uint32_t sb = sbase + s * STAGE_BYTES;
        cp16(sb + ST_AHI + sAoff, gAhi + s * BKT);
        cp16(sb + ST_ALO + sAoff, gAlo + s * BKT);
        cp16(sb + ST_BHI + sBoff, gBhi + (size_t)s * BKT * N);
        cp16(sb + ST_BLO + sBoff, gBlo + (size_t)s * BKT * N);
        cp_commit();
    }

    for (int t = 0; t < NT; t++) {
        cp_wait1();
        __syncthreads();
        const uint32_t sb = sbase + (t & 1) * STAGE_BYTES;

        uint32_t ahi[2][4], alo[2][4];
#pragma unroll
        for (int mf = 0; mf < 2; mf++) {
            const uint32_t arow_ch = (uint32_t)((a_srow0 + mf * 16) * A_CH + a_kch) * 16;
            ldsm4(ahi[mf], sb + ST_AHI + arow_ch);
            ldsm4(alo[mf], sb + ST_ALO + arow_ch);
        }
#pragma unroll
        for (int nb = 0; nb < 4; nb++) {
            uint32_t bh[4], bl[4];
            const uint32_t boff = (uint32_t)(b_srow * B_CH + b_nch0 + nb * 2) * 16;
            ldsm4t(bh, sb + ST_BHI + boff);
            ldsm4t(bl, sb + ST_BLO + boff);
#pragma unroll
            for (int mf = 0; mf < 2; mf++) {
#pragma unroll
                for (int sub = 0; sub < 2; sub++) {
                    float* c = acc[mf][nb * 2 + sub];
                    mma_bf16(c, ahi[mf], bh[sub * 2], bh[sub * 2 + 1]);
                    mma_bf16(c, ahi[mf], bl[sub * 2], bl[sub * 2 + 1]);
                    mma_bf16(c, alo[mf], bh[sub * 2], bh[sub * 2 + 1]);
                }
            }
        }
        __syncthreads();
        if (t + 2 < NT) {
            const int kt = t + 2;
            const uint32_t sb2 = sbase + (t & 1) * STAGE_BYTES;
            cp16(sb2 + ST_AHI + sAoff, gAhi + kt * BKT);
            cp16(sb2 + ST_ALO + sAoff, gAlo + kt * BKT);
            cp16(sb2 + ST_BHI + sBoff, gBhi + (size_t)kt * BKT * N);
            cp16(sb2 + ST_BLO + sBoff, gBlo + (size_t)kt * BKT * N);
            cp_commit();
        } else {
            cp_commit();
        }
    }

    const int g  = lane >> 2;
    const int tg = lane & 3;
#pragma unroll
    for (int mf = 0; mf < 2; mf++) {
        const int row0 = bm + wm + mf * 16 + g;
#pragma unroll
        for (int nf = 0; nf < 8; nf++) {
            const int col = bn + wn + nf * 8 + tg * 2;
            const float2 bv = *(const float2*)(bias + col);
            float2 o0, o1;
            o0.x = acc[mf][nf][0] + bv.x;
            o0.y = acc[mf][nf][1] + bv.y;
            o1.x = acc[mf][nf][2] + bv.x;
            o1.y = acc[mf][nf][3] + bv.y;
            *(float2*)(C + (size_t)row0 * N + col)       = o0;
            *(float2*)(C + (size_t)(row0 + 8) * N + col) = o1;
        }
    }
}

// ---------------- K^T V partials ----------------
__global__ __launch_bounds__(256) void ktv_partial_kernel(
    const float* __restrict__ Kp, const float* __restrict__ Vp,
    float* __restrict__ Mpart)
{
    const int bh    = blockIdx.x;
    const int chunk = blockIdx.y;
    const int b = bh >> 4, h = bh & 15;
    const int kbase = b * NSEQ + chunk * 256;
    const int col   = h * DH;

    __shared__ float Ks[8][64];
    __shared__ float Vs[8][64];
    const int tid = threadIdx.x;
    const int tdk = (tid & 15) * 4;
    const int tdv = (tid >> 4) * 4;
    const int lane = tid & 127;
    const int lr = lane >> 4;
    const int lc = (lane & 15) * 4;

    float acc[4][4];
#pragma unroll
    for (int i = 0; i < 4; i++)
#pragma unroll
        for (int j = 0; j < 4; j++) acc[i][j] = 0.f;

    for (int k0 = 0; k0 < 256; k0 += 8) {
        const float* src = (tid < 128) ? Kp : Vp;
        float* dst = (tid < 128) ? &Ks[lr][lc] : &Vs[lr][lc];
        *(float4*)dst = *(const float4*)(src + (size_t)(kbase + k0 + lr) * D_MODEL + col + lc);
        __syncthreads();
#pragma unroll
        for (int r = 0; r < 8; r++) {
            float kv[4], vv[4];
            *(float4*)kv = *(const float4*)&Ks[r][tdk];
            *(float4*)vv = *(const float4*)&Vs[r][tdv];
#pragma unroll
            for (int i = 0; i < 4; i++)
#pragma unroll
                for (int j = 0; j < 4; j++) acc[i][j] = fmaf(kv[i], vv[j], acc[i][j]);
        }
        __syncthreads();
    }
    float* Mp = Mpart + ((size_t)chunk * (NB * NH) + bh) * (DH * DH);
#pragma unroll
    for (int i = 0; i < 4; i++)
#pragma unroll
        for (int j = 0; j < 4; j++) Mp[(tdk + i) * DH + tdv + j] = acc[i][j];
}

__global__ void m_reduce_kernel(const float* __restrict__ Mpart, float* __restrict__ Mo)
{
    const int i = blockIdx.x * blockDim.x + threadIdx.x;
    if (i < NB * NH * DH * DH) {
        float s = 0.f;
#pragma unroll
        for (int c = 0; c < 8; c++) s += Mpart[(size_t)c * (NB * NH * DH * DH) + i];
        Mo[i] = s;
    }
}

// ---------------- tensor-core attention ----------------
// CTA: 128 queries x one (b,h). K-tiles of 64 keys, double-buffered cp.async.
// Scores via mma 3x split-bf16 (SCALE*log2e folded into Q), base-2 online softmax.
// smem rows padded to 9 chunks (144B) for conflict-free ldmatrix.
#define KT     64
#define QT     128
#define ACH    9
#define A_ROWB (ACH * 16)                  // 144 bytes per row
#define AST_LO (KT * A_ROWB)               // 9216: Klo offset within stage
#define ASTAGE (2 * KT * A_ROWB)           // 18432 per stage

__global__ __launch_bounds__(256) void attn_mma_kernel(
    const __nv_bfloat16* __restrict__ Qhi, const __nv_bfloat16* __restrict__ Qlo,
    const __nv_bfloat16* __restrict__ Khi, const __nv_bfloat16* __restrict__ Klo,
    const float* __restrict__ Qg, const float* __restrict__ S,
    const float* __restrict__ Mo, float* __restrict__ O)
{
    __shared__ __align__(16) unsigned char sm[2 * ASTAGE];   // Q load -> K stages -> M
    __shared__ float sm_m[2][QT];
    __shared__ float sm_d[2][QT];
    __shared__ float beta_s[QT];

    const int q0 = blockIdx.x * QT;
    const int h  = blockIdx.y;
    const int b  = blockIdx.z;
    const int rowbase = b * NSEQ;
    const int col = h * DH;
    const int tid  = threadIdx.x;
    const int lane = tid & 31;
    const int w    = tid >> 5;
    const int wm   = (w & 3) * 32;    // warp query offset
    const int wn   = (w >> 2) * 32;   // warp key offset within tile
    const int wnid = w >> 2;

    const uint32_t sbase = (uint32_t)__cvta_generic_to_shared(&sm[0]);
    const int mIdx = lane >> 3, mrow = lane & 7;

    // ---- load Q tile (hi into [0,18432), lo into [18432,36864)) ----
    {
#pragma unroll
        for (int it = 0; it < 8; it++) {
            const int idx = tid + it * 256;        // 0..2047
            const int part = idx >> 10;            // 0 hi, 1 lo
            const int r = (idx >> 3) & 127;
            const int c = idx & 7;
            const __nv_bfloat16* src = part ? Qlo : Qhi;
            cp16(sbase + part * ASTAGE + (uint32_t)(r * ACH + c) * 16,
                 src + (size_t)(rowbase + q0 + r) * D_MODEL + col + c * 8);
        }
        cp_commit();
        cp_wait0();
        __syncthreads();
    }

    // ---- Q fragments to registers ----
    uint32_t qhi[2][4][4], qlo[2][4][4];
#pragma unroll
    for (int mf = 0; mf < 2; mf++) {
        const int r = wm + mf * 16 + (mIdx & 1) * 8 + mrow;
#pragma unroll
        for (int ks = 0; ks < 4; ks++) {
            const uint32_t off = (uint32_t)(r * ACH + ks * 2 + (mIdx >> 1)) * 16;
            ldsm4(qhi[mf][ks], sbase + off);
            ldsm4(qlo[mf][ks], sbase + ASTAGE + off);
        }
    }
    __syncthreads();   // Q consumed; smem free for K stages

    // ---- K pipeline prologue ----
    const int NKT = NSEQ / KT;   // 32
#pragma unroll
    for (int s = 0; s < 2; s++) {
        const uint32_t sb = sbase + s * ASTAGE;
#pragma unroll
        for (int it = 0; it < 4; it++) {
            const int idx = tid + it * 256;        // 0..1023
            const int part = idx >> 9;             // 0 hi, 1 lo
            const int r = (idx >> 3) & 63;
            const int c = idx & 7;
            const __nv_bfloat16* src = part ? Klo : Khi;
            cp16(sb + part * AST_LO + (uint32_t)(r * ACH + c) * 16,
                 src + (size_t)(rowbase + s * KT + r) * D_MODEL + col + c * 8);
        }
        cp_commit();
    }

    float m_t[4] = {-1e30f, -1e30f, -1e30f, -1e30f};
    float d_t[4] = {0.f, 0.f, 0.f, 0.f};

    // B-frag ldsm addressing: key = wn + p*16 + (mIdx>>1)*8 + mrow, chunk = 2ks + (mIdx&1)
    const int b_keyoff = (mIdx >> 1) * 8 + mrow;
    const int b_ch     = mIdx & 1;

    for (int t = 0; t < NKT; t++) {
        cp_wait1();
        __syncthreads();
        const uint32_t sb = sbase + (t & 1) * ASTAGE;

        float acc[2][4][4];
#pragma unroll
        for (int i = 0; i < 2; i++)
#pragma unroll
            for (int j = 0; j < 4; j++)
#pragma unroll
                for (int q = 0; q < 4; q++) acc[i][j][q] = 0.f;

#pragma unroll
        for (int ks = 0; ks < 4; ks++) {
            uint32_t bh[2][4], bl[2][4];
#pragma unroll
            for (int p = 0; p < 2; p++) {
                const uint32_t off = (uint32_t)((wn + p * 16 + b_keyoff) * ACH + ks * 2 + b_ch) * 16;
                ldsm4(bh[p], sb + off);
                ldsm4(bl[p], sb + AST_LO + off);
            }
#pragma unroll
            for (int mf = 0; mf < 2; mf++) {
#pragma unroll
                for (int p = 0; p < 2; p++) {
#pragma unroll
                    for (int s2 = 0; s2 < 2; s2++) {
                        float* c = acc[mf][p * 2 + s2];
                        mma_bf16(c, qhi[mf][ks], bh[p][s2 * 2], bh[p][s2 * 2 + 1]);
                        mma_bf16(c, qhi[mf][ks], bl[p][s2 * 2], bl[p][s2 * 2 + 1]);
                        mma_bf16(c, qlo[mf][ks], bh[p][s2 * 2], bh[p][s2 * 2 + 1]);
                    }
                }
            }
        }

        // online base-2 softmax stats (scores already have SCALE*log2e folded in)
#pragma unroll
        for (int mf = 0; mf < 2; mf++) {
#pragma unroll
            for (int rr = 0; rr < 2; rr++) {
                const int si = mf * 2 + rr;
                float v[8];
#pragma unroll
                for (int nf = 0; nf < 4; nf++) {
                    v[nf * 2]     = acc[mf][nf][rr * 2];
                    v[nf * 2 + 1] = acc[mf][nf][rr * 2 + 1];
                }
                float mx = v[0];
#pragma unroll
                for (int j = 1; j < 8; j++) mx = fmaxf(mx, v[j]);
                const float mn = fmaxf(m_t[si], mx);
                float s = d_t[si] * ex2f(m_t[si] - mn);
#pragma unroll
                for (int j = 0; j < 8; j++) s += ex2f(v[j] - mn);
                d_t[si] = s;
                m_t[si] = mn;
            }
        }

        __syncthreads();
        if (t + 2 < NKT) {
            const uint32_t sb2 = sbase + (t & 1) * ASTAGE;
            const int kb = (t + 2) * KT;
#pragma unroll
            for (int it = 0; it < 4; it++) {
                const int idx = tid + it * 256;
                const int part = idx >> 9;
                const int r = (idx >> 3) & 63;
                const int c = idx & 7;
                const __nv_bfloat16* src = part ? Klo : Khi;
                cp16(sb2 + part * AST_LO + (uint32_t)(r * ACH + c) * 16,
                     src + (size_t)(rowbase + kb + r) * D_MODEL + col + c * 8);
            }
            cp_commit();
        } else {
            cp_commit();
        }
    }

    // ---- reduce stats: quad (4 threads share a row) via shfl ----
    const int g = lane >> 2;
#pragma unroll
    for (int i = 0; i < 4; i++) {
#pragma unroll
        for (int off = 1; off <= 2; off <<= 1) {
            const float mo = __shfl_xor_sync(0xffffffffu, m_t[i], off);
            const float dd = __shfl_xor_sync(0xffffffffu, d_t[i], off);
            const float mn = fmaxf(m_t[i], mo);
            d_t[i] = d_t[i] * ex2f(m_t[i] - mn) + dd * ex2f(mo - mn);
            m_t[i] = mn;
        }
    }
    if ((lane & 3) == 0) {
#pragma unroll
        for (int i = 0; i < 4; i++) {
            const int r = wm + (i >> 1) * 16 + (i & 1) * 8 + g;
            sm_m[wnid][r] = m_t[i];
            sm_d[wnid][r] = d_t[i];
        }
    }
    __syncthreads();

    // ---- load M (64x64 fp32) into smem (reuse stage area) ----
    float* Msh = (float*)sm;
    {
        const float* Mp = Mo + (size_t)(b * NH + h) * (DH * DH);
#pragma unroll
        for (int it = 0; it < 4; it++) {
            const int i4 = tid + it * 256;           // 1024 float4
            ((float4*)Msh)[i4] = ((const float4*)Mp)[i4];
        }
    }

    // ---- per-row: combine 2 n-warps, lang term, beta ----
    if (tid < QT) {
        const int q = tid;
        const float m0 = sm_m[0][q], m1 = sm_m[1][q];
        const float m = fmaxf(m0, m1);
        const float D = sm_d[0][q] * ex2f(m0 - m) + sm_d[1][q] * ex2f(m1 - m);
        const float* Qrow = Qg + (size_t)(rowbase + q0 + q) * D_MODEL + col;
        const float* Srow = S  + (size_t)(rowbase + q0 + q) * D_MODEL + col;
        float lg = 0.f;
#pragma unroll 16
        for (int d = 0; d < DH; d++) lg = fmaf(Qrow[d], Srow[d], lg);
        lg *= K2SCALE;
        const float mf2 = fmaxf(m, lg);
        const float Df = D * ex2f(m - mf2) + ex2f(lg - mf2);
        beta_s[q] = ex2f(lg - mf2) / Df;
    }
    __syncthreads();

    // ---- epilogue: att_v = SCALE*q @ M ; out = beta*s + (1-beta)*att_v ----
    {
        const int q   = tid >> 1;
        const int dv0 = (tid & 1) * 32;
        const float* Qrow = Qg + (size_t)(rowbase + q0 + q) * D_MODEL + col;
        float acc2[32];
#pragma unroll
        for (int j = 0; j < 32; j++) acc2[j] = 0.f;
#pragma unroll 8
        for (int dk = 0; dk < DH; dk++) {
            const float qv = Qrow[dk] * SCALE;
            const float* Mrow = Msh + dk * DH + dv0;
#pragma unroll
            for (int j = 0; j < 32; j++) acc2[j] = fmaf(qv, Mrow[j], acc2[j]);
        }
        const float beta = beta_s[q];
        const float omb  = 1.f - beta;
        const float* Srow = S + (size_t)(rowbase + q0 + q) * D_MODEL + col + dv0;
        float* Orow = O + (size_t)(rowbase + q0 + q) * D_MODEL + col + dv0;
#pragma unroll
        for (int j4 = 0; j4 < 32; j4 += 4) {
            float4 sv = *(const float4*)(Srow + j4);
            float4 o;
            o.x = beta * sv.x + omb * acc2[j4 + 0];
            o.y = beta * sv.y + omb * acc2[j4 + 1];
            o.z = beta * sv.z + omb * acc2[j4 + 2];
            o.w = beta * sv.w + omb * acc2[j4 + 3];
            *(float4*)(Orow + j4) = o;
        }
    }
}

// ---------------- launch ----------------
extern "C" void kernel_launch(void* const* d_in, const int* in_sizes, int n_in,
                              void* d_out, int out_size)
{
    (void)in_sizes; (void)n_in; (void)out_size;
    const float* queries = (const float*)d_in[0];
    const float* keys    = (const float*)d_in[1];
    const float* values  = (const float*)d_in[2];
    const float* langf   = (const float*)d_in[3];
    const float* Wq = (const float*)d_in[4];
    const float* bq = (const float*)d_in[5];
    const float* Wk = (const float*)d_in[6];
    const float* bk = (const float*)d_in[7];
    const float* Wv = (const float*)d_in[8];
    const float* bv = (const float*)d_in[9];
    const float* Ws = (const float*)d_in[10];
    const float* bs = (const float*)d_in[11];
    const float* Wo = (const float*)d_in[12];
    const float* bo = (const float*)d_in[13];

    float *Qp, *Kp, *Vp, *Sp, *Op, *MPp, *Mp;
    __nv_bfloat16 *Ahi, *Alo, *Bhi, *Blo, *Qhi, *Qlo, *Khi, *Klo;
    cudaGetSymbolAddress((void**)&Qp,  g_Q);
    cudaGetSymbolAddress((void**)&Kp,  g_K);
    cudaGetSymbolAddress((void**)&Vp,  g_V);
    cudaGetSymbolAddress((void**)&Sp,  g_S);
    cudaGetSymbolAddress((void**)&Op,  g_O);
    cudaGetSymbolAddress((void**)&MPp, g_Mpart);
    cudaGetSymbolAddress((void**)&Mp,  g_M);
    cudaGetSymbolAddress((void**)&Ahi, g_Ahi);
    cudaGetSymbolAddress((void**)&Alo, g_Alo);
    cudaGetSymbolAddress((void**)&Bhi, g_Bhi);
    cudaGetSymbolAddress((void**)&Blo, g_Blo);
    cudaGetSymbolAddress((void**)&Qhi, g_Qhi);
    cudaGetSymbolAddress((void**)&Qlo, g_Qlo);
    cudaGetSymbolAddress((void**)&Khi, g_Khi);
    cudaGetSymbolAddress((void**)&Klo, g_Klo);

    const int nA4 = ROWS * D_MODEL / 4;
    const int nW4 = D_MODEL * D_MODEL / 4;
    dim3 gemm_grid(D_MODEL / 128, ROWS / 128);

    struct { const float* X; const float* W; const float* bvec; float* C; } proj[4] = {
        {queries, Wq, bq, Qp}, {keys, Wk, bk, Kp}, {values, Wv, bv, Vp}, {langf, Ws, bs, Sp}
    };
    for (int p = 0; p < 4; p++) {
        split_bf16_kernel<<<(nA4 + 255) / 256, 256>>>(proj[p].X, Ahi, Alo, nA4, 1.0f);
        split_bf16_kernel<<<(nW4 + 255) / 256, 256>>>(proj[p].W, Bhi, Blo, nW4, 1.0f);
        gemm_bf16x3_bias<<<gemm_grid, 256>>>(Ahi, Alo, Bhi, Blo, proj[p].bvec, proj[p].C,
                                             ROWS, D_MODEL, D_MODEL);
    }

    // splits for tensor-core attention (Q carries SCALE*log2e)
    split_bf16_kernel<<<(nA4 + 255) / 256, 256>>>(Qp, Qhi, Qlo, nA4, K2SCALE);
    split_bf16_kernel<<<(nA4 + 255) / 256, 256>>>(Kp, Khi, Klo, nA4, 1.0f);

    ktv_partial_kernel<<<dim3(NB * NH, 8), 256>>>(Kp, Vp, MPp);
    m_reduce_kernel<<<(NB * NH * DH * DH + 255) / 256, 256>>>(MPp, Mp);

    attn_mma_kernel<<<dim3(NSEQ / QT, NH, NB), 256>>>(Qhi, Qlo, Khi, Klo, Qp, Sp, Mp, Op);

    split_bf16_kernel<<<(nA4 + 255) / 256, 256>>>(Op, Ahi, Alo, nA4, 1.0f);
    split_bf16_kernel<<<(nW4 + 255) / 256, 256>>>(Wo, Bhi, Blo, nW4, 1.0f);
    gemm_bf16x3_bias<<<gemm_grid, 256>>>(Ahi, Alo, Bhi, Blo, bo, (float*)d_out,
                                         ROWS, D_MODEL, D_MODEL);
}